// round 12
// baseline (speedup 1.0000x reference)
#include <cuda_runtime.h>
#include <cuda_bf16.h>
#include <cstdint>

#define NUM_PINS_MAX   2000000
#define MAX_BLOCKS     4096

// Scratch: packed (x,y) per pin, per-block partials, reduction counter.
__device__ float2       g_pinxy[NUM_PINS_MAX];
__device__ double       g_partials[MAX_BLOCKS];
__device__ unsigned int g_counter = 0;

// ---------------------------------------------------------------------------
// Kernel A: pack x/y halves of pin_pos into float2 array, 4 pins per thread.
// Trigger fires at BLOCK START: it only gates the secondary's launch (memory
// visibility is handled by the secondary's cudaGridDependencySynchronize),
// so the pair kernel can co-schedule with pack and overlap its direct phase.
// g_pinxy address taken in DEVICE code only (host-side __device__ symbol ref
// hits ATS host shadow memory on GB300).
// ---------------------------------------------------------------------------
__global__ void __launch_bounds__(256)
pack_pins_kernel(const float4* __restrict__ x4,
                 const float4* __restrict__ y4,
                 int n4)                      // n_pins / 4
{
    cudaTriggerProgrammaticLaunchCompletion();
    float4* __restrict__ out4 = reinterpret_cast<float4*>(g_pinxy);
    int i = blockIdx.x * blockDim.x + threadIdx.x;
    if (i < n4) {
        float4 x = x4[i];
        float4 y = y4[i];
        out4[2 * i]     = make_float4(x.x, y.x, x.y, y.y);
        out4[2 * i + 1] = make_float4(x.z, y.z, x.w, y.w);
    }
}

// ---------------------------------------------------------------------------
// Kernel B: pair loop in two phases.
//  Phase 1 (pre-sync, overlaps pack): quads [0, n_split) gathered DIRECTLY
//    from the SoA pin_pos halves (4x4B gathers/pair — pack-independent).
//  cudaGridDependencySynchronize(): pack grid complete + stores visible.
//  Phase 2: quads [n_split, n_quads) via packed g_pinxy (R10/R11 hot loop,
//    unchanged: __ldcg 8B gathers, __ldcs streaming).
// Fused last-block final reduction. Fixed split -> deterministic.
// ---------------------------------------------------------------------------
__global__ void __launch_bounds__(256, 8)
pair_attraction_kernel(const int4*   __restrict__ pairs4,   // [n_quads] (a0,b0,a1,b1)
                       const float2* __restrict__ w2,       // [n_quads]
                       const float*  __restrict__ xs,       // pin_pos[0:n)
                       const float*  __restrict__ ys,       // pin_pos[n:2n)
                       int n_split,
                       int n_quads,
                       float* __restrict__ out)
{
    const int tid0   = blockIdx.x * blockDim.x + threadIdx.x;
    const int stride = gridDim.x * blockDim.x;

    float acc0 = 0.0f, acc1 = 0.0f;

    // ---- Phase 1: direct SoA gathers, runs while pack executes ----
    for (int i = tid0; i < n_split; i += stride) {
        int4   p = __ldcs(&pairs4[i]);
        float2 w = __ldcs(&w2[i]);

        float xa0 = __ldcg(&xs[p.x]), xb0 = __ldcg(&xs[p.y]);
        float xa1 = __ldcg(&xs[p.z]), xb1 = __ldcg(&xs[p.w]);
        float ya0 = __ldcg(&ys[p.x]), yb0 = __ldcg(&ys[p.y]);
        float ya1 = __ldcg(&ys[p.z]), yb1 = __ldcg(&ys[p.w]);

        float dx0 = xa0 - xb0, dy0 = ya0 - yb0;
        float dx1 = xa1 - xb1, dy1 = ya1 - yb1;

        acc0 = fmaf(w.x, fmaf(dx0, dx0, dy0 * dy0), acc0);
        acc1 = fmaf(w.y, fmaf(dx1, dx1, dy1 * dy1), acc1);
    }

    // ---- wait for pack grid completion (memory visible) ----
    cudaGridDependencySynchronize();

    // ---- Phase 2: packed gathers (best-measured hot loop, unchanged) ----
    const float2* __restrict__ pinxy = g_pinxy;

    for (int i = tid0 + n_split; i < n_quads; i += stride) {
        int4   p = __ldcs(&pairs4[i]);
        float2 w = __ldcs(&w2[i]);

        float2 a0 = __ldcg(&pinxy[p.x]);
        float2 b0 = __ldcg(&pinxy[p.y]);
        float2 a1 = __ldcg(&pinxy[p.z]);
        float2 b1 = __ldcg(&pinxy[p.w]);

        float dx0 = a0.x - b0.x, dy0 = a0.y - b0.y;
        float dx1 = a1.x - b1.x, dy1 = a1.y - b1.y;

        acc0 = fmaf(w.x, fmaf(dx0, dx0, dy0 * dy0), acc0);
        acc1 = fmaf(w.y, fmaf(dx1, dx1, dy1 * dy1), acc1);
    }

    float acc = acc0 + acc1;

    // warp reduce (fp32)
    #pragma unroll
    for (int off = 16; off > 0; off >>= 1)
        acc += __shfl_xor_sync(0xFFFFFFFFu, acc, off);

    // block reduce via shared (double for cross-warp combine)
    __shared__ double warp_sums[8];   // 256 threads = 8 warps
    int lane = threadIdx.x & 31;
    int wid  = threadIdx.x >> 5;
    if (lane == 0) warp_sums[wid] = (double)acc;
    __syncthreads();

    if (wid == 0) {
        double v = (lane < 8) ? warp_sums[lane] : 0.0;
        #pragma unroll
        for (int off = 4; off > 0; off >>= 1)
            v += __shfl_xor_sync(0xFFFFFFFFu, v, off);
        if (lane == 0) g_partials[blockIdx.x] = v;
    }

    // ---- last-block final reduction ----
    __shared__ bool is_last;
    if (threadIdx.x == 0) {
        __threadfence();  // make this block's partial visible
        unsigned int old = atomicAdd(&g_counter, 1u);
        is_last = (old == gridDim.x - 1);
    }
    __syncthreads();

    if (is_last) {
        __threadfence();  // acquire: see all other blocks' partials
        double v = 0.0;
        for (int i = threadIdx.x; i < (int)gridDim.x; i += blockDim.x)
            v += g_partials[i];

        #pragma unroll
        for (int off = 16; off > 0; off >>= 1)
            v += __shfl_xor_sync(0xFFFFFFFFu, v, off);

        __shared__ double fin[8];
        if (lane == 0) fin[wid] = v;
        __syncthreads();

        if (wid == 0) {
            double s = (lane < 8) ? fin[lane] : 0.0;
            #pragma unroll
            for (int off = 4; off > 0; off >>= 1)
                s += __shfl_xor_sync(0xFFFFFFFFu, s, off);
            if (lane == 0) {
                out[0] = (float)s;
                g_counter = 0;   // reset for next graph replay (deterministic)
            }
        }
    }
}

// ---------------------------------------------------------------------------
// Launcher: pack (trigger at start), then pair with PDL. The pair kernel's
// direct-gather phase hides pack entirely.
// ---------------------------------------------------------------------------
extern "C" void kernel_launch(void* const* d_in, const int* in_sizes, int n_in,
                              void* d_out, int out_size) {
    const float* pin_pos = (const float*)d_in[0];
    const float* weights = (const float*)d_in[1];
    const int*   pairs   = (const int*)d_in[2];
    // d_in[3] = pin_mask (unused by the reference computation)

    int n_pins  = in_sizes[0] / 2;          // 2,000,000
    int n_pairs = in_sizes[2] / 2;          // 10,000,000
    int n_quads = n_pairs / 2;              // 5,000,000

    int n_split = 262144;                   // ~5% of quads, sized to pack dur
    if (n_split > n_quads) n_split = n_quads;

    float* out = (float*)d_out;

    // A: pack pins (vectorized, 4 pins/thread, trigger at block start)
    {
        int n4      = n_pins / 4;           // 500,000
        int threads = 256;
        int blocks  = (n4 + threads - 1) / threads;
        pack_pins_kernel<<<blocks, threads>>>(
            (const float4*)pin_pos,
            (const float4*)(pin_pos + n_pins),
            n4);
    }

    // B: two-phase pair loop + fused final reduction, PDL-chained to pack
    {
        int threads = 256;
        int blocks  = 148 * 8;              // 1184 blocks (best measured)
        if (blocks > MAX_BLOCKS) blocks = MAX_BLOCKS;

        cudaLaunchConfig_t cfg = {};
        cfg.gridDim  = dim3((unsigned)blocks, 1, 1);
        cfg.blockDim = dim3((unsigned)threads, 1, 1);
        cfg.dynamicSmemBytes = 0;
        cfg.stream = 0;   // same (capture) stream as the pack launch

        cudaLaunchAttribute attrs[1];
        attrs[0].id = cudaLaunchAttributeProgrammaticStreamSerialization;
        attrs[0].val.programmaticStreamSerializationAllowed = 1;
        cfg.attrs    = attrs;
        cfg.numAttrs = 1;

        const int4*   pairs4 = (const int4*)pairs;
        const float2* w2     = (const float2*)weights;
        const float*  xs     = pin_pos;
        const float*  ys     = pin_pos + n_pins;
        cudaLaunchKernelEx(&cfg, pair_attraction_kernel,
                           pairs4, w2, xs, ys, n_split, n_quads, out);
    }
}